// round 1
// baseline (speedup 1.0000x reference)
#include <cuda_runtime.h>
#include <math.h>

#define BB 16
#define TT 2048
#define DD 2048
#define CC 100

#define ALPHA 0.0005f
#define MARGIN 100.0f
#define EPS_C 1e-7f

// ---------------- scratch (device globals; no allocation) ----------------
__device__ float g_colsum[2][BB * DD];  // [tensor][b*D + d] column sums over t
__device__ float g_sq[BB * CC];         // sum_t (sup - pmask)^2 per (b,c)
__device__ float g_pos[BB * CC];        // sum_t pmask per (b,c)
__device__ float g_st[1];               // sum (cas_s - cas_t)^2

// ---------------- zero scratch ----------------
__global__ void zero_kernel() {
    const int N0 = 2 * BB * DD;           // colsum
    const int N1 = N0 + BB * CC;          // sq
    const int N2 = N1 + BB * CC;          // pos
    const int N  = N2 + 1;                // st
    for (int i = blockIdx.x * blockDim.x + threadIdx.x; i < N;
         i += gridDim.x * blockDim.x) {
        if (i < N0)      ((float*)g_colsum)[i] = 0.0f;
        else if (i < N1) g_sq[i - N0] = 0.0f;
        else if (i < N2) g_pos[i - N1] = 0.0f;
        else             g_st[0] = 0.0f;
    }
}

// ---------------- feat column sums ----------------
// grid: (T/FT_TCHUNK, D/1024, 2*B), block: 256
// Each block: tensor = z>>4, b = z&15, d-range [blockIdx.y*1024, +1024),
// t-range [blockIdx.x*FT_TCHUNK, +FT_TCHUNK). float4 per thread, coalesced.
#define FT_TCHUNK 128
__global__ __launch_bounds__(256) void feat_kernel(
    const float* __restrict__ fa, const float* __restrict__ fb) {
    const int z = blockIdx.z;
    const int tensor = z >> 4;
    const int b = z & 15;
    const float* __restrict__ f = tensor ? fb : fa;

    const int d0 = blockIdx.y * 1024 + (threadIdx.x << 2);
    const size_t base = (size_t)b * TT * DD + (size_t)blockIdx.x * FT_TCHUNK * DD + d0;
    const float4* __restrict__ p = (const float4*)(f + base);

    float4 acc = make_float4(0.f, 0.f, 0.f, 0.f);
#pragma unroll 8
    for (int t = 0; t < FT_TCHUNK; t++) {
        float4 v = __ldg(p + (size_t)t * (DD / 4));
        acc.x += v.x; acc.y += v.y; acc.z += v.z; acc.w += v.w;
    }
    float* cs = &g_colsum[tensor][b * DD + d0];
    atomicAdd(cs + 0, acc.x);
    atomicAdd(cs + 1, acc.y);
    atomicAdd(cs + 2, acc.z);
    atomicAdd(cs + 3, acc.w);
}

// ---------------- [B,T,C] tensors: sup / pos / st ----------------
// block = 128 threads; lane handles class c = threadIdx.x (active if c < 100).
// Consecutive lanes -> consecutive floats -> coalesced rows of 400B.
// Register accumulators only; 201 global atomics per block at the end.
#define BT_TCHUNK 64
__global__ __launch_bounds__(128) void btc_kernel(
    const float* __restrict__ gt, const float* __restrict__ sup,
    const float* __restrict__ cs, const float* __restrict__ ct) {
    const int b = blockIdx.y;
    const int t0 = blockIdx.x * BT_TCHUNK;
    const int c = threadIdx.x;

    float sq = 0.f, pos = 0.f, st = 0.f;
    if (c < CC) {
        size_t base = (size_t)b * TT * CC + (size_t)t0 * CC + c;
#pragma unroll 4
        for (int t = 0; t < BT_TCHUNK; t++) {
            size_t o = base + (size_t)t * CC;
            float g = __ldg(gt + o);
            float s = __ldg(sup + o);
            float x = __ldg(cs + o);
            float y = __ldg(ct + o);
            float pm = (g > 0.5f) ? 1.f : 0.f;
            float d = s - pm;
            sq += d * d;
            pos += pm;
            float e = x - y;
            st += e * e;
        }
        atomicAdd(&g_sq[b * CC + c], sq);
        atomicAdd(&g_pos[b * CC + c], pos);
    }
    // block reduce st
    __shared__ float sh[128];
    sh[threadIdx.x] = st;
    __syncthreads();
    for (int s = 64; s > 0; s >>= 1) {
        if (threadIdx.x < s) sh[threadIdx.x] += sh[threadIdx.x + s];
        __syncthreads();
    }
    if (threadIdx.x == 0) atomicAdd(g_st, sh[0]);
}

// ---------------- final assembly (1 block, 256 threads) ----------------
__device__ __forceinline__ float block_reduce_256(float v, float* red) {
    int tid = threadIdx.x;
    red[tid] = v;
    __syncthreads();
    for (int s = 128; s > 0; s >>= 1) {
        if (tid < s) red[tid] += red[tid + s];
        __syncthreads();
    }
    float r = red[0];
    __syncthreads();
    return r;
}

__global__ __launch_bounds__(256) void final_kernel(
    const float* __restrict__ score_act, const float* __restrict__ score_bkg,
    const float* __restrict__ label, float* __restrict__ out) {
    __shared__ float red[256];
    __shared__ float lsum[BB];
    __shared__ float n2[2 * BB];
    const int tid = threadIdx.x;

    // per-row label sums
    if (tid < BB) {
        float s = 0.f;
        for (int c = 0; c < CC; c++) s += label[tid * CC + c];
        lsum[tid] = s;
    }
    __syncthreads();

    // loss_cls / loss_be accumulation over [B,C]
    float acc_cls = 0.f, acc_be = 0.f;
    const float tb = 1.0f / CC;
    for (int i = tid; i < BB * CC; i += 256) {
        float p = score_act[i];
        p = fminf(fmaxf(p, EPS_C), 1.0f - EPS_C);
        float t = label[i] / lsum[i / CC];
        acc_cls += t * logf(p) + (1.0f - t) * log1pf(-p);

        float q = score_bkg[i];
        q = fminf(fmaxf(q, EPS_C), 1.0f - EPS_C);
        acc_be += tb * logf(q) + (1.0f - tb) * log1pf(-q);
    }
    float sum_cls = block_reduce_256(acc_cls, red);
    float sum_be  = block_reduce_256(acc_be, red);

    // squared norms of mean features: 32 combos (tensor, b)
    for (int k = 0; k < 2 * BB; k++) {
        int tensor = k >> 4, b = k & 15;
        float s = 0.f;
        for (int i = tid; i < DD; i += 256) {
            float v = g_colsum[tensor][b * DD + i] * (1.0f / TT);
            s += v * v;
        }
        s = block_reduce_256(s, red);
        if (tid == 0) n2[k] = s;
        __syncthreads();
    }

    // loss_sup: sum of valid norms, count of valid
    float acc_sup = 0.f, acc_cnt = 0.f;
    for (int i = tid; i < BB * CC; i += 256) {
        if (g_pos[i] > 0.f) {
            acc_sup += sqrtf(g_sq[i]);
            acc_cnt += 1.f;
        }
    }
    float sum_sup = block_reduce_256(acc_sup, red);
    float sum_cnt = block_reduce_256(acc_cnt, red);

    if (tid == 0) {
        float loss_cls = -sum_cls / (float)(BB * CC);
        float loss_be  = -sum_be  / (float)(BB * CC);

        float um = 0.f;
        for (int b = 0; b < BB; b++) {
            float an = sqrtf(n2[b]);
            float bn = sqrtf(n2[BB + b]);
            float la = fmaxf(MARGIN - an, 0.f);
            float v = la + bn;
            um += v * v;
        }
        float loss_um = um / (float)BB;

        float loss_sup = sum_sup / fmaxf(sum_cnt, 1.0f);
        float loss_st  = g_st[0] / (float)(BB * TT * CC);

        float total = loss_cls + ALPHA * loss_um + loss_be + loss_sup + loss_st;
        out[0] = total;
        out[1] = loss_cls;
        out[2] = loss_be;
        out[3] = loss_um;
        out[4] = loss_sup;
        out[5] = loss_st;
    }
}

// ---------------- launch ----------------
extern "C" void kernel_launch(void* const* d_in, const int* in_sizes, int n_in,
                              void* d_out, int out_size) {
    const float* score_act = (const float*)d_in[0];
    const float* score_bkg = (const float*)d_in[1];
    const float* feat_act  = (const float*)d_in[2];
    const float* feat_bkg  = (const float*)d_in[3];
    const float* label     = (const float*)d_in[4];
    const float* gt        = (const float*)d_in[5];
    const float* sup_cas   = (const float*)d_in[6];
    const float* cas_s     = (const float*)d_in[7];
    const float* cas_t     = (const float*)d_in[8];

    zero_kernel<<<64, 256>>>();
    feat_kernel<<<dim3(TT / FT_TCHUNK, DD / 1024, 2 * BB), 256>>>(feat_act, feat_bkg);
    btc_kernel<<<dim3(TT / BT_TCHUNK, BB), 128>>>(gt, sup_cas, cas_s, cas_t);
    final_kernel<<<1, 256>>>(score_act, score_bkg, label, (float*)d_out);
}

// round 4
// speedup vs baseline: 1.1765x; 1.1765x over previous
#include <cuda_runtime.h>
#include <math.h>

#define BB 16
#define TT 2048
#define DD 2048
#define CC 100

#define ALPHA 0.0005f
#define MARGIN 100.0f
#define EPS_C 1e-7f

// ---------------- scratch (device globals; no allocation) ----------------
__device__ float g_colsum[2][BB * DD];  // [tensor][b*D + d] column sums over t
__device__ float g_sq[BB * CC];         // sum_t (sup - pmask)^2 per (b,c)
__device__ float g_pos[BB * CC];        // sum_t pmask per (b,c)
__device__ float g_st[1];               // sum (cas_s - cas_t)^2
__device__ float g_n2[2 * BB];          // squared norms of mean features

// ---------------- zero scratch ----------------
__global__ void zero_kernel() {
    const int N0 = 2 * BB * DD;           // colsum
    const int N1 = N0 + BB * CC;          // sq
    const int N2 = N1 + BB * CC;          // pos
    const int N  = N2 + 1;                // st
    for (int i = blockIdx.x * blockDim.x + threadIdx.x; i < N;
         i += gridDim.x * blockDim.x) {
        if (i < N0)      ((float*)g_colsum)[i] = 0.0f;
        else if (i < N1) g_sq[i - N0] = 0.0f;
        else if (i < N2) g_pos[i - N1] = 0.0f;
        else             g_st[0] = 0.0f;
    }
}

// ---------------- feat column sums ----------------
// grid: (T/FT_TCHUNK, D/1024, 2*B), block: 256. float4 per thread, coalesced.
#define FT_TCHUNK 128
__global__ __launch_bounds__(256) void feat_kernel(
    const float* __restrict__ fa, const float* __restrict__ fb) {
    const int z = blockIdx.z;
    const int tensor = z >> 4;
    const int b = z & 15;
    const float* __restrict__ f = tensor ? fb : fa;

    const int d0 = blockIdx.y * 1024 + (threadIdx.x << 2);
    const size_t base = (size_t)b * TT * DD + (size_t)blockIdx.x * FT_TCHUNK * DD + d0;
    const float4* __restrict__ p = (const float4*)(f + base);

    float4 acc = make_float4(0.f, 0.f, 0.f, 0.f);
#pragma unroll 8
    for (int t = 0; t < FT_TCHUNK; t++) {
        float4 v = __ldg(p + (size_t)t * (DD / 4));
        acc.x += v.x; acc.y += v.y; acc.z += v.z; acc.w += v.w;
    }
    float* cs = &g_colsum[tensor][b * DD + d0];
    atomicAdd(cs + 0, acc.x);
    atomicAdd(cs + 1, acc.y);
    atomicAdd(cs + 2, acc.z);
    atomicAdd(cs + 3, acc.w);
}

// ---------------- [B,T,C] tensors: sup / pos / st ----------------
// lane = class c (c<100 active), register accumulators, end-of-block atomics.
#define BT_TCHUNK 32
__global__ __launch_bounds__(128) void btc_kernel(
    const float* __restrict__ gt, const float* __restrict__ sup,
    const float* __restrict__ cs, const float* __restrict__ ct) {
    const int b = blockIdx.y;
    const int t0 = blockIdx.x * BT_TCHUNK;
    const int c = threadIdx.x;

    float sq = 0.f, pos = 0.f, st = 0.f;
    if (c < CC) {
        size_t base = (size_t)b * TT * CC + (size_t)t0 * CC + c;
#pragma unroll 4
        for (int t = 0; t < BT_TCHUNK; t++) {
            size_t o = base + (size_t)t * CC;
            float g = __ldg(gt + o);
            float s = __ldg(sup + o);
            float x = __ldg(cs + o);
            float y = __ldg(ct + o);
            float pm = (g > 0.5f) ? 1.f : 0.f;
            float d = s - pm;
            sq += d * d;
            pos += pm;
            float e = x - y;
            st += e * e;
        }
        atomicAdd(&g_sq[b * CC + c], sq);
        atomicAdd(&g_pos[b * CC + c], pos);
    }
    // block reduce st
    __shared__ float sh[128];
    sh[threadIdx.x] = st;
    __syncthreads();
    for (int s = 64; s > 0; s >>= 1) {
        if (threadIdx.x < s) sh[threadIdx.x] += sh[threadIdx.x + s];
        __syncthreads();
    }
    if (threadIdx.x == 0) atomicAdd(g_st, sh[0]);
}

// ---------------- norm reduction: 32 blocks, one per (tensor,b) -------------
__global__ __launch_bounds__(256) void norm_kernel() {
    const int k = blockIdx.x;            // 0..31
    const int tensor = k >> 4, b = k & 15;
    const float* __restrict__ cs = &g_colsum[tensor][b * DD];

    float s = 0.f;
    for (int i = threadIdx.x; i < DD; i += 256) {
        float v = cs[i] * (1.0f / TT);
        s += v * v;
    }
    __shared__ float red[256];
    red[threadIdx.x] = s;
    __syncthreads();
    for (int w = 128; w > 0; w >>= 1) {
        if (threadIdx.x < w) red[threadIdx.x] += red[threadIdx.x + w];
        __syncthreads();
    }
    if (threadIdx.x == 0) g_n2[k] = red[0];
}

// ---------------- final assembly (1 block, 256 threads, all-parallel) --------
__device__ __forceinline__ float block_reduce_256(float v, float* red) {
    int tid = threadIdx.x;
    red[tid] = v;
    __syncthreads();
    for (int s = 128; s > 0; s >>= 1) {
        if (tid < s) red[tid] += red[tid + s];
        __syncthreads();
    }
    float r = red[0];
    __syncthreads();
    return r;
}

__global__ __launch_bounds__(256) void final_kernel(
    const float* __restrict__ score_act, const float* __restrict__ score_bkg,
    const float* __restrict__ label, float* __restrict__ out) {
    __shared__ float red[256];
    __shared__ float lsum[BB];
    const int tid = threadIdx.x;

    // parallel label row-sums via shared atomics
    if (tid < BB) lsum[tid] = 0.f;
    __syncthreads();
    for (int i = tid; i < BB * CC; i += 256)
        atomicAdd(&lsum[i / CC], label[i]);
    __syncthreads();

    // loss_cls / loss_be accumulation over [B,C]
    float acc_cls = 0.f, acc_be = 0.f;
    const float tb = 1.0f / CC;
    for (int i = tid; i < BB * CC; i += 256) {
        float p = score_act[i];
        p = fminf(fmaxf(p, EPS_C), 1.0f - EPS_C);
        float t = label[i] / lsum[i / CC];
        acc_cls += t * logf(p) + (1.0f - t) * log1pf(-p);

        float q = score_bkg[i];
        q = fminf(fmaxf(q, EPS_C), 1.0f - EPS_C);
        acc_be += tb * logf(q) + (1.0f - tb) * log1pf(-q);
    }
    float sum_cls = block_reduce_256(acc_cls, red);
    float sum_be  = block_reduce_256(acc_be, red);

    // loss_sup: sum of valid norms, count of valid
    float acc_sup = 0.f, acc_cnt = 0.f;
    for (int i = tid; i < BB * CC; i += 256) {
        if (g_pos[i] > 0.f) {
            acc_sup += sqrtf(g_sq[i]);
            acc_cnt += 1.f;
        }
    }
    float sum_sup = block_reduce_256(acc_sup, red);
    float sum_cnt = block_reduce_256(acc_cnt, red);

    // loss_um from precomputed squared norms (16 lanes active)
    float um_part = 0.f;
    if (tid < BB) {
        float an = sqrtf(g_n2[tid]);
        float bn = sqrtf(g_n2[BB + tid]);
        float la = fmaxf(MARGIN - an, 0.f);
        float v = la + bn;
        um_part = v * v;
    }
    float sum_um = block_reduce_256(um_part, red);

    if (tid == 0) {
        float loss_cls = -sum_cls / (float)(BB * CC);
        float loss_be  = -sum_be  / (float)(BB * CC);
        float loss_um  = sum_um / (float)BB;
        float loss_sup = sum_sup / fmaxf(sum_cnt, 1.0f);
        float loss_st  = g_st[0] / (float)(BB * TT * CC);

        float total = loss_cls + ALPHA * loss_um + loss_be + loss_sup + loss_st;
        out[0] = total;
        out[1] = loss_cls;
        out[2] = loss_be;
        out[3] = loss_um;
        out[4] = loss_sup;
        out[5] = loss_st;
    }
}

// ---------------- launch ----------------
extern "C" void kernel_launch(void* const* d_in, const int* in_sizes, int n_in,
                              void* d_out, int out_size) {
    const float* score_act = (const float*)d_in[0];
    const float* score_bkg = (const float*)d_in[1];
    const float* feat_act  = (const float*)d_in[2];
    const float* feat_bkg  = (const float*)d_in[3];
    const float* label     = (const float*)d_in[4];
    const float* gt        = (const float*)d_in[5];
    const float* sup_cas   = (const float*)d_in[6];
    const float* cas_s     = (const float*)d_in[7];
    const float* cas_t     = (const float*)d_in[8];

    zero_kernel<<<64, 256>>>();
    feat_kernel<<<dim3(TT / FT_TCHUNK, DD / 1024, 2 * BB), 256>>>(feat_act, feat_bkg);
    btc_kernel<<<dim3(TT / BT_TCHUNK, BB), 128>>>(gt, sup_cas, cas_s, cas_t);
    norm_kernel<<<2 * BB, 256>>>();
    final_kernel<<<1, 256>>>(score_act, score_bkg, label, (float*)d_out);
}

// round 5
// speedup vs baseline: 1.3577x; 1.1540x over previous
#include <cuda_runtime.h>
#include <math.h>

#define BB 16
#define TT 2048
#define DD 2048
#define CC 100

#define ALPHA 0.0005f
#define MARGIN 100.0f
#define EPS_C 1e-7f

#define FEAT_BLOCKS 1024   // 16 tchunks x 2 dchunks x 32 (tensor,b)
#define BTC_BLOCKS  512    // 32 tchunks(64t) x 16 b
#define TOTAL_BLOCKS (FEAT_BLOCKS + BTC_BLOCKS)

// ---------------- scratch (device globals; zero-init at load) ----------------
// Invariant: zero at kernel_launch entry; tail_kernel re-zeros after reading.
__device__ float g_colsum[2][BB * DD];  // [tensor][b*D + d] column sums over t
__device__ float g_sq[BB * CC];         // sum_t (sup - pmask)^2 per (b,c)
__device__ float g_pos[BB * CC];        // sum_t pmask per (b,c)
__device__ float g_st[1];               // sum (cas_s - cas_t)^2

// ---------------- fused streaming kernel ----------------
__global__ __launch_bounds__(256) void main_kernel(
    const float* __restrict__ fa, const float* __restrict__ fb,
    const float* __restrict__ gt, const float* __restrict__ sup,
    const float* __restrict__ cas_s, const float* __restrict__ cas_t) {
    const int bz = blockIdx.x;
    const int tid = threadIdx.x;

    if (bz < FEAT_BLOCKS) {
        // ---- feat column sums: tile = [128 t x 1024 d] ----
        const int tch = bz & 15;
        const int dch = (bz >> 4) & 1;
        const int z = bz >> 5;            // 0..31
        const int tensor = z >> 4;
        const int b = z & 15;
        const float* __restrict__ f = tensor ? fb : fa;

        const int d0 = dch * 1024 + (tid << 2);
        const size_t base = (size_t)b * TT * DD + (size_t)tch * 128 * DD + d0;
        const float4* __restrict__ p = (const float4*)(f + base);

        float4 acc = make_float4(0.f, 0.f, 0.f, 0.f);
#pragma unroll 16
        for (int t = 0; t < 128; t++) {
            float4 v = __ldcs(p + (size_t)t * (DD / 4));
            acc.x += v.x; acc.y += v.y; acc.z += v.z; acc.w += v.w;
        }
        float* cs = &g_colsum[tensor][b * DD + d0];
        atomicAdd(cs + 0, acc.x);
        atomicAdd(cs + 1, acc.y);
        atomicAdd(cs + 2, acc.z);
        atomicAdd(cs + 3, acc.w);
    } else {
        // ---- [B,T,C] streams: sup / pos / st ----
        // block covers 64 t-rows; two 128-thread halves cover 32 t each.
        const int i = bz - FEAT_BLOCKS;   // 0..511
        const int b = i >> 5;
        const int tci = i & 31;
        const int half = tid >> 7;        // 0 or 1
        const int c = tid & 127;
        const int t0 = tci * 64 + half * 32;

        float sq = 0.f, pos = 0.f, st = 0.f;
        if (c < CC) {
            size_t base = (size_t)b * TT * CC + (size_t)t0 * CC + c;
#pragma unroll 4
            for (int t = 0; t < 32; t++) {
                size_t o = base + (size_t)t * CC;
                float g = __ldcs(gt + o);
                float s = __ldcs(sup + o);
                float x = __ldcs(cas_s + o);
                float y = __ldcs(cas_t + o);
                float pm = (g > 0.5f) ? 1.f : 0.f;
                float d = s - pm;
                sq += d * d;
                pos += pm;
                float e = x - y;
                st += e * e;
            }
            atomicAdd(&g_sq[b * CC + c], sq);
            atomicAdd(&g_pos[b * CC + c], pos);
        }
        __shared__ float sh[256];
        sh[tid] = st;
        __syncthreads();
        for (int s = 128; s > 0; s >>= 1) {
            if (tid < s) sh[tid] += sh[tid + s];
            __syncthreads();
        }
        if (tid == 0) atomicAdd(g_st, sh[0]);
    }
}

// ---------------- tail: norms + BCEs + assembly + scratch reset --------------
__device__ __forceinline__ float block_reduce_1024(float v, float* red) {
    int tid = threadIdx.x;
    red[tid] = v;
    __syncthreads();
    for (int s = 512; s > 0; s >>= 1) {
        if (tid < s) red[tid] += red[tid + s];
        __syncthreads();
    }
    float r = red[0];
    __syncthreads();
    return r;
}

__global__ __launch_bounds__(1024) void tail_kernel(
    const float* __restrict__ score_act, const float* __restrict__ score_bkg,
    const float* __restrict__ label, float* __restrict__ out) {
    __shared__ float red[1024];
    __shared__ float lsum[BB];
    __shared__ float n2s[2 * BB];
    const int tid = threadIdx.x;
    const int w = tid >> 5;     // warp 0..31 -> (tensor,b)
    const int lane = tid & 31;

    // ---- per-(tensor,b) squared norm of mean feature; zero colsum after read
    {
        float* cs = &g_colsum[w >> 4][(w & 15) * DD];
        float s = 0.f;
#pragma unroll 8
        for (int i = lane; i < DD; i += 32) {
            float v = cs[i] * (1.0f / TT);
            s += v * v;
            cs[i] = 0.f;
        }
#pragma unroll
        for (int o = 16; o > 0; o >>= 1)
            s += __shfl_xor_sync(0xFFFFFFFFu, s, o);
        if (lane == 0) n2s[w] = s;
    }

    // ---- label row-sums (shared atomics)
    if (tid < BB) lsum[tid] = 0.f;
    __syncthreads();
    for (int i = tid; i < BB * CC; i += 1024)
        atomicAdd(&lsum[i / CC], label[i]);
    __syncthreads();

    // ---- BCE terms over [B,C]
    float acc_cls = 0.f, acc_be = 0.f;
    const float tb = 1.0f / CC;
    for (int i = tid; i < BB * CC; i += 1024) {
        float p = score_act[i];
        p = fminf(fmaxf(p, EPS_C), 1.0f - EPS_C);
        float t = label[i] / lsum[i / CC];
        acc_cls += t * logf(p) + (1.0f - t) * log1pf(-p);

        float q = score_bkg[i];
        q = fminf(fmaxf(q, EPS_C), 1.0f - EPS_C);
        acc_be += tb * logf(q) + (1.0f - tb) * log1pf(-q);
    }
    float sum_cls = block_reduce_1024(acc_cls, red);
    float sum_be  = block_reduce_1024(acc_be, red);

    // ---- loss_sup; zero g_sq/g_pos after reading
    float acc_sup = 0.f, acc_cnt = 0.f;
    for (int i = tid; i < BB * CC; i += 1024) {
        float pv = g_pos[i];
        float qv = g_sq[i];
        if (pv > 0.f) {
            acc_sup += sqrtf(qv);
            acc_cnt += 1.f;
        }
        g_pos[i] = 0.f;
        g_sq[i] = 0.f;
    }
    float sum_sup = block_reduce_1024(acc_sup, red);
    float sum_cnt = block_reduce_1024(acc_cnt, red);

    // ---- loss_um from n2s (16 lanes active)
    float um_part = 0.f;
    if (tid < BB) {
        float an = sqrtf(n2s[tid]);
        float bn = sqrtf(n2s[BB + tid]);
        float la = fmaxf(MARGIN - an, 0.f);
        float v = la + bn;
        um_part = v * v;
    }
    float sum_um = block_reduce_1024(um_part, red);

    if (tid == 0) {
        float st_sum = g_st[0];
        g_st[0] = 0.f;

        float loss_cls = -sum_cls / (float)(BB * CC);
        float loss_be  = -sum_be  / (float)(BB * CC);
        float loss_um  = sum_um / (float)BB;
        float loss_sup = sum_sup / fmaxf(sum_cnt, 1.0f);
        float loss_st  = st_sum / (float)(BB * TT * CC);

        float total = loss_cls + ALPHA * loss_um + loss_be + loss_sup + loss_st;
        out[0] = total;
        out[1] = loss_cls;
        out[2] = loss_be;
        out[3] = loss_um;
        out[4] = loss_sup;
        out[5] = loss_st;
    }
}

// ---------------- launch ----------------
extern "C" void kernel_launch(void* const* d_in, const int* in_sizes, int n_in,
                              void* d_out, int out_size) {
    const float* score_act = (const float*)d_in[0];
    const float* score_bkg = (const float*)d_in[1];
    const float* feat_act  = (const float*)d_in[2];
    const float* feat_bkg  = (const float*)d_in[3];
    const float* label     = (const float*)d_in[4];
    const float* gt        = (const float*)d_in[5];
    const float* sup_cas   = (const float*)d_in[6];
    const float* cas_s     = (const float*)d_in[7];
    const float* cas_t     = (const float*)d_in[8];

    main_kernel<<<TOTAL_BLOCKS, 256>>>(feat_act, feat_bkg, gt, sup_cas, cas_s, cas_t);
    tail_kernel<<<1, 1024>>>(score_act, score_bkg, label, (float*)d_out);
}